// round 14
// baseline (speedup 1.0000x reference)
#include <cuda_runtime.h>
#include <cuda_bf16.h>
#include <cuda_fp8.h>
#include <cstdint>
#include <math.h>

#define BATCH 4
#define DIM   128
#define NPTS  4096
#define NB    (BATCH*NPTS)
#define MC    32            // m-chunks
#define MPER  128           // m per chunk
#define NBLK  (MC*BATCH)    // 128
#define INV_T 14.285714285714286f
#define QS    64.0f         // fp8 pre-scale (folded out in finisher)
#define QS4   16777216.0f   // 64^4
#define QS2   4096.0f       // 64^2
#define TAILB 260           // 256 frobenius blocks + 4 s1 blocks

// fp8 tile: [128 d rows][128 m + 16 pad] = 144 B row stride (conflict-free LDSM)
#define TSTRIDE 144

// ---- device scratch (no allocations allowed) ----
__device__ uint32_t g_gpart[2097152];      // bf16x2 gram partials, 8.4 MB
__device__ float g_spart[2*BATCH*MC*DIM];  // per-d column-sum partials (x64 scaled)
__device__ float g_dgpart[NBLK];
__device__ float g_dg2part[NBLK];
__device__ float g_fpart[256];
__device__ float g_s1[BATCH];
__device__ unsigned int g_ctr;             // zero-init; reset by finisher

// =============================== PTX helpers ===============================
__device__ __forceinline__ uint32_t smem_u32(const void* p) {
    uint32_t a;
    asm("{ .reg .u64 t; cvta.to.shared.u64 t, %1; cvt.u32.u64 %0, t; }"
        : "=r"(a) : "l"(p));
    return a;
}
__device__ __forceinline__ void ldsm_x4(uint32_t* r, uint32_t addr) {
    asm volatile("ldmatrix.sync.aligned.m8n8.x4.shared.b16 {%0,%1,%2,%3}, [%4];"
        : "=r"(r[0]), "=r"(r[1]), "=r"(r[2]), "=r"(r[3]) : "r"(addr));
}
__device__ __forceinline__ void mma_fp8(float* c, const uint32_t* a,
                                        uint32_t b0, uint32_t b1) {
    asm volatile("mma.sync.aligned.m16n8k32.row.col.f32.e4m3.e4m3.f32 "
        "{%0,%1,%2,%3}, {%4,%5,%6,%7}, {%8,%9}, {%0,%1,%2,%3};"
        : "+f"(c[0]), "+f"(c[1]), "+f"(c[2]), "+f"(c[3])
        : "r"(a[0]), "r"(a[1]), "r"(a[2]), "r"(a[3]), "r"(b0), "r"(b1));
}
__device__ __forceinline__ uint32_t bf2u(__nv_bfloat162 v) {
    return *(uint32_t*)&v;
}
__device__ __forceinline__ float blo(uint32_t u) { return __uint_as_float(u << 16); }
__device__ __forceinline__ float bhi(uint32_t u) { return __uint_as_float(u & 0xffff0000u); }
__device__ __forceinline__ uint32_t pack_fp8x4(float a, float b, float c, float d) {
    __nv_fp8x2_storage_t lo =
        __nv_cvt_float2_to_fp8x2(make_float2(a, b), __NV_SATFINITE, __NV_E4M3);
    __nv_fp8x2_storage_t hi =
        __nv_cvt_float2_to_fp8x2(make_float2(c, d), __NV_SATFINITE, __NV_E4M3);
    return (uint32_t)lo | ((uint32_t)hi << 16);
}

// smem byte layout (scratch aliases tile region — each alias dead before reuse)
#define SB_QB   0            // fp8 q tile, 18432
#define SB_KB   18432        // fp8 k tile -> 36864
#define SB_RQ   0            // alias: 16 warps x 128 m x 4B = 8192
#define SB_RK   8192
#define SB_RD   16384        // ends 24576 < 36864
#define SB_IQ   36864        // 128 f (x64-scaled inv norms)
#define SB_IK   37376
#define SB_NS   37888        // 3 x 128 reduced norm/dot sums = 1536 B
#define SB_SCR  39424        // 16 floats -> 39488
#define SB_CS   39488        // column-sum scratch: 32 lanes x 257 f = 32896
#define SB_TOTAL 72384

// ===========================================================================
// k_main: 512 thr, grid (32,4). R13 pipeline + (a) 384-thread phase-2a
// reduce, (b) PDL launch_dependents after the final store.
// ===========================================================================
__global__ __launch_bounds__(512, 1) void k_main(const float* __restrict__ q,
                                                 const float* __restrict__ k) {
    extern __shared__ char smc[];
    char*  qb  = smc + SB_QB;
    char*  kb  = smc + SB_KB;
    float* rq  = (float*)(smc + SB_RQ);
    float* rk  = (float*)(smc + SB_RK);
    float* rd  = (float*)(smc + SB_RD);
    float* iq  = (float*)(smc + SB_IQ);
    float* ik  = (float*)(smc + SB_IK);
    float* ns  = (float*)(smc + SB_NS);
    float* scr = (float*)(smc + SB_SCR);
    float* csS = (float*)(smc + SB_CS);    // [lane][257], slot = which*128+d

    int tid = threadIdx.x, wid = tid >> 5, lane = tid & 31;
    int cblk = blockIdx.x, b = blockIdx.y;
    int m0 = cblk * MPER;
    int m4 = lane * 4;

    // ---- phase 1: single global read; norm/dot partials; raw bf16 in regs
    const float* qg = q + (size_t)b * DIM * NPTS + m0 + m4;
    const float* kg = k + (size_t)b * DIM * NPTS + m0 + m4;
    uint2 qr[8], kr[8];
    float sq0 = 0.f, sq1 = 0.f, sq2 = 0.f, sq3 = 0.f;
    float sk0 = 0.f, sk1 = 0.f, sk2 = 0.f, sk3 = 0.f;
    float dt0 = 0.f, dt1 = 0.f, dt2 = 0.f, dt3 = 0.f;
#pragma unroll
    for (int it = 0; it < 8; it++) {
        int d = it * 16 + wid;
        float4 vq = *(const float4*)(qg + (size_t)d * NPTS);
        float4 vk = *(const float4*)(kg + (size_t)d * NPTS);
        sq0 += fabsf(vq.x); sq1 += fabsf(vq.y); sq2 += fabsf(vq.z); sq3 += fabsf(vq.w);
        sk0 += fabsf(vk.x); sk1 += fabsf(vk.y); sk2 += fabsf(vk.z); sk3 += fabsf(vk.w);
        dt0 += vq.x * vk.x; dt1 += vq.y * vk.y; dt2 += vq.z * vk.z; dt3 += vq.w * vk.w;
        qr[it] = make_uint2(bf2u(__float22bfloat162_rn(make_float2(vq.x, vq.y))),
                            bf2u(__float22bfloat162_rn(make_float2(vq.z, vq.w))));
        kr[it] = make_uint2(bf2u(__float22bfloat162_rn(make_float2(vk.x, vk.y))),
                            bf2u(__float22bfloat162_rn(make_float2(vk.z, vk.w))));
    }
    *(float4*)(rq + wid * 128 + m4) = make_float4(sq0, sq1, sq2, sq3);
    *(float4*)(rk + wid * 128 + m4) = make_float4(sk0, sk1, sk2, sk3);
    *(float4*)(rd + wid * 128 + m4) = make_float4(dt0, dt1, dt2, dt3);
    __syncthreads();

    // ---- phase 2a: 384 threads reduce (array, m) over 16 warps ------------
    if (tid < 384) {
        int arr = tid >> 7, m = tid & 127;
        const float* basep = (const float*)(smc + arr * 8192);
        float a0 = 0.f, a1 = 0.f, a2 = 0.f, a3 = 0.f;
#pragma unroll
        for (int w = 0; w < 16; w += 4) {
            a0 += basep[(w + 0) * 128 + m];
            a1 += basep[(w + 1) * 128 + m];
            a2 += basep[(w + 2) * 128 + m];
            a3 += basep[(w + 3) * 128 + m];
        }
        ns[arr * 128 + m] = (a0 + a1) + (a2 + a3);
    }
    __syncthreads();

    // ---- phase 2b: inv norms (x64 for fp8); dg/dg2 block totals -----------
    if (tid < 128) {
        float iqv = 1.f / fmaxf(ns[tid], 1e-12f);
        float ikv = 1.f / fmaxf(ns[128 + tid], 1e-12f);
        float dt  = ns[256 + tid];
        iq[tid] = iqv * QS;
        ik[tid] = ikv * QS;
        float dg = dt * iqv * ikv;          // exact fp32, unscaled
        float dg2 = dg * dg;
#pragma unroll
        for (int o = 16; o; o >>= 1) {
            dg  += __shfl_down_sync(0xffffffffu, dg, o);
            dg2 += __shfl_down_sync(0xffffffffu, dg2, o);
        }
        if (lane == 0) { scr[wid] = dg; scr[4 + wid] = dg2; }
    }
    __syncthreads();
    if (tid == 0) {
        int blk = b * MC + cblk;
        g_dgpart[blk]  = scr[0] + scr[1] + scr[2] + scr[3];
        g_dg2part[blk] = scr[4] + scr[5] + scr[6] + scr[7];
    }

    // ---- phase 3: normalize (fp32) -> fp8 tiles; cs partials to smem ------
    {
        float4 iqv = *(float4*)(iq + m4);
        float4 ikv = *(float4*)(ik + m4);
#pragma unroll
        for (int it = 0; it < 8; it++) {
            int d = it * 16 + wid;
            float x0 = blo(qr[it].x) * iqv.x, x1 = bhi(qr[it].x) * iqv.y;
            float x2 = blo(qr[it].y) * iqv.z, x3 = bhi(qr[it].y) * iqv.w;
            float y0 = blo(kr[it].x) * ikv.x, y1 = bhi(kr[it].x) * ikv.y;
            float y2 = blo(kr[it].y) * ikv.z, y3 = bhi(kr[it].y) * ikv.w;
            uint32_t off = (uint32_t)(d * TSTRIDE) + (uint32_t)m4;
            *(uint32_t*)(qb + off) = pack_fp8x4(x0, x1, x2, x3);
            *(uint32_t*)(kb + off) = pack_fp8x4(y0, y1, y2, y3);
            csS[lane * 257 + d]       = (x0 + x1) + (x2 + x3);
            csS[lane * 257 + 128 + d] = (y0 + y1) + (y2 + y3);
        }
    }
    __syncthreads();

    // ---- phase 3b: column-sum reduce (256 threads, conflict-free LDS) -----
    if (tid < 256) {
        float a0 = 0.f, a1 = 0.f, a2 = 0.f, a3 = 0.f;
#pragma unroll
        for (int l = 0; l < 32; l += 4) {
            a0 += csS[(l + 0) * 257 + tid];
            a1 += csS[(l + 1) * 257 + tid];
            a2 += csS[(l + 2) * 257 + tid];
            a3 += csS[(l + 3) * 257 + tid];
        }
        int which = tid >> 7, d = tid & 127;
        g_spart[((size_t)(which * BATCH + b) * MC + cblk) * DIM + d]
            = (a0 + a1) + (a2 + a3);
    }
    // no extra sync: phase 4 reads only the tiles (already synced)

    // ---- phase 4: fp8 grams. warps 0-7 -> Gq, 8-15 -> Gk -----------------
    int which = wid >> 3;
    int wrow = wid & 7;
    uint32_t base = smem_u32(which ? kb : qb);
    int grp = lane >> 3;
    uint32_t arow_off = (uint32_t)((wrow * 16 + ((grp & 1) << 3) + (lane & 7)) * TSTRIDE
                                   + ((grp >> 1) << 4));
    uint32_t brow_off = (uint32_t)((((grp & 1) << 3) + (lane & 7)) * TSTRIDE
                                   + ((grp >> 1) << 4));
    int r  = lane >> 2;
    int cp = (lane & 3) << 1;
    int d1r = wrow * 16 + r;

    float c[64];
#pragma unroll
    for (int i = 0; i < 64; i++) c[i] = 0.f;

#pragma unroll
    for (int ks = 0; ks < 4; ks++) {           // K=32 fp8 per mma, 4*32=128 m
        uint32_t a[4];
        ldsm_x4(a, base + arow_off + ks * 32);
#pragma unroll
        for (int bt = 0; bt < 8; bt++) {
            uint32_t bb[4];
            ldsm_x4(bb, base + brow_off + (uint32_t)(bt * 16 * TSTRIDE) + ks * 32);
            mma_fp8(c + bt * 8,     a, bb[0], bb[2]);
            mma_fp8(c + bt * 8 + 4, a, bb[1], bb[3]);
        }
    }

    uint32_t* outp = g_gpart
        + ((size_t)(which * BATCH + b) * MC + cblk) * 8192;   // u32 pairs
#pragma unroll
    for (int bt = 0; bt < 8; bt++) {
#pragma unroll
        for (int h = 0; h < 2; h++) {
            int col = bt * 16 + h * 8 + cp;
            const float* cc = c + bt * 8 + h * 4;
            outp[(d1r * 128 + col) >> 1] =
                bf2u(__float22bfloat162_rn(make_float2(cc[0], cc[1])));
            outp[((d1r + 8) * 128 + col) >> 1] =
                bf2u(__float22bfloat162_rn(make_float2(cc[2], cc[3])));
        }
    }

    // PDL: this block's results are written — signal dependent launch.
    asm volatile("griddepcontrol.launch_dependents;" ::: "memory");
}

// ===========================================================================
// k_tail: grid 260, 256 thr. PDL secondary: waits on k_main via
// griddepcontrol.wait, then does the whole reduction.
//  blk < 256: frobenius (8 independent __ldcg uint4 loads per thread).
//  blk >= 256: s1 for batch blk-256.
//  Counter finisher computes the final scalar.
// ===========================================================================
__global__ __launch_bounds__(256) void k_tail(float* __restrict__ out) {
    __shared__ float smQ[256][8];
    __shared__ float smK[256][8];
    __shared__ float rr[8];
    __shared__ bool lastf;
    int tid = threadIdx.x, lane = tid & 31;
    int blk = blockIdx.x;

    // PDL: ensure k_main's grid is complete + memory visible
    asm volatile("griddepcontrol.wait;" ::: "memory");

    if (blk < 256) {
        int bb = blk >> 6;                          // batch
        int pos = (blk & 63) * 32 + (tid & 31);     // uint4 position 0..2047
        int cs = tid >> 5;                          // csplit 0..7 (4 chunks)
        const uint4* bq = (const uint4*)g_gpart
                        + (size_t)(0 * BATCH + bb) * MC * 2048 + pos
                        + (size_t)(cs * 4) * 2048;
        const uint4* bk = (const uint4*)g_gpart
                        + (size_t)(1 * BATCH + bb) * MC * 2048 + pos
                        + (size_t)(cs * 4) * 2048;
        uint4 q0 = __ldcg(bq);
        uint4 q1 = __ldcg(bq + 2048);
        uint4 q2 = __ldcg(bq + 2 * 2048);
        uint4 q3 = __ldcg(bq + 3 * 2048);
        uint4 k0 = __ldcg(bk);
        uint4 k1 = __ldcg(bk + 2048);
        uint4 k2 = __ldcg(bk + 2 * 2048);
        uint4 k3 = __ldcg(bk + 3 * 2048);

        float* oq = &smQ[tid][0];
        float* ok = &smK[tid][0];
        oq[0] = (blo(q0.x) + blo(q1.x)) + (blo(q2.x) + blo(q3.x));
        oq[1] = (bhi(q0.x) + bhi(q1.x)) + (bhi(q2.x) + bhi(q3.x));
        oq[2] = (blo(q0.y) + blo(q1.y)) + (blo(q2.y) + blo(q3.y));
        oq[3] = (bhi(q0.y) + bhi(q1.y)) + (bhi(q2.y) + bhi(q3.y));
        oq[4] = (blo(q0.z) + blo(q1.z)) + (blo(q2.z) + blo(q3.z));
        oq[5] = (bhi(q0.z) + bhi(q1.z)) + (bhi(q2.z) + bhi(q3.z));
        oq[6] = (blo(q0.w) + blo(q1.w)) + (blo(q2.w) + blo(q3.w));
        oq[7] = (bhi(q0.w) + bhi(q1.w)) + (bhi(q2.w) + bhi(q3.w));
        ok[0] = (blo(k0.x) + blo(k1.x)) + (blo(k2.x) + blo(k3.x));
        ok[1] = (bhi(k0.x) + bhi(k1.x)) + (bhi(k2.x) + bhi(k3.x));
        ok[2] = (blo(k0.y) + blo(k1.y)) + (blo(k2.y) + blo(k3.y));
        ok[3] = (bhi(k0.y) + bhi(k1.y)) + (bhi(k2.y) + bhi(k3.y));
        ok[4] = (blo(k0.z) + blo(k1.z)) + (blo(k2.z) + blo(k3.z));
        ok[5] = (bhi(k0.z) + bhi(k1.z)) + (bhi(k2.z) + bhi(k3.z));
        ok[6] = (blo(k0.w) + blo(k1.w)) + (blo(k2.w) + blo(k3.w));
        ok[7] = (bhi(k0.w) + bhi(k1.w)) + (bhi(k2.w) + bhi(k3.w));
        __syncthreads();

        // combine 8 csplits in fixed order (full 32-chunk sums), then product
        int lp = tid >> 3, e = tid & 7;             // local pos, elem
        float aq = 0.f, ak = 0.f;
#pragma unroll
        for (int s = 0; s < 8; s++) {
            aq += smQ[s * 32 + lp][e];
            ak += smK[s * 32 + lp][e];
        }
        float f = aq * ak;
#pragma unroll
        for (int o = 16; o; o >>= 1) f += __shfl_down_sync(0xffffffffu, f, o);
        if (lane == 0) rr[tid >> 5] = f;
        __syncthreads();
        if (tid == 0) {
            float t = 0.f;
#pragma unroll
            for (int i = 0; i < 8; i++) t += rr[i];
            g_fpart[blk] = t;
        }
    } else {
        int b = blk - 256;
        float* SQ = &smQ[0][0];                     // 512 floats used
        float* SK = &smK[0][0];
        if (tid < 128) {
            int d4 = tid & 31, half = tid >> 5;     // chunk 4-way split
            const float4* pq = (const float4*)(g_spart
                + (size_t)(0 * BATCH + b) * MC * DIM) + d4 + (size_t)(half * 8) * 32;
            const float4* pk = (const float4*)(g_spart
                + (size_t)(1 * BATCH + b) * MC * DIM) + d4 + (size_t)(half * 8) * 32;
            float4 sq = make_float4(0.f, 0.f, 0.f, 0.f);
            float4 sk = make_float4(0.f, 0.f, 0.f, 0.f);
#pragma unroll
            for (int c = 0; c < 8; c++) {
                float4 tq = __ldcg(pq + (size_t)c * 32);
                float4 tk = __ldcg(pk + (size_t)c * 32);
                sq.x += tq.x; sq.y += tq.y; sq.z += tq.z; sq.w += tq.w;
                sk.x += tk.x; sk.y += tk.y; sk.z += tk.z; sk.w += tk.w;
            }
            // layout: [d (=d4*4+e)][half] -> SQ[(d4*4+e)*4+half]
            SQ[(d4 * 4 + 0) * 4 + half] = sq.x;
            SQ[(d4 * 4 + 1) * 4 + half] = sq.y;
            SQ[(d4 * 4 + 2) * 4 + half] = sq.z;
            SQ[(d4 * 4 + 3) * 4 + half] = sq.w;
            SK[(d4 * 4 + 0) * 4 + half] = sk.x;
            SK[(d4 * 4 + 1) * 4 + half] = sk.y;
            SK[(d4 * 4 + 2) * 4 + half] = sk.z;
            SK[(d4 * 4 + 3) * 4 + half] = sk.w;
        }
        __syncthreads();
        if (tid < 128) {
            // full 32-chunk sums per d (fixed order), then product
            float aq = ((SQ[tid * 4 + 0] + SQ[tid * 4 + 1])
                      + (SQ[tid * 4 + 2] + SQ[tid * 4 + 3]));
            float ak = ((SK[tid * 4 + 0] + SK[tid * 4 + 1])
                      + (SK[tid * 4 + 2] + SK[tid * 4 + 3]));
            float v = aq * ak;
#pragma unroll
            for (int o = 16; o; o >>= 1)
                v += __shfl_down_sync(0xffffffffu, v, o);
            if (lane == 0) rr[tid >> 5] = v;
        }
        __syncthreads();
        if (tid == 0) g_s1[b] = rr[0] + rr[1] + rr[2] + rr[3];
    }

    // ---- finisher: last of the 260 blocks computes the loss ---------------
    __syncthreads();
    if (tid == 0) {
        __threadfence();
        lastf = (atomicAdd(&g_ctr, 1u) == (unsigned)(TAILB - 1));
    }
    __syncthreads();
    if (lastf) {
        float* red = &smQ[0][0];                    // 256 floats
        const float halfT2 = 0.5f * INV_T * INV_T;
        float v = (halfT2 / QS4) * __ldcg(g_fpart + tid);
        if (tid < BATCH) v += (INV_T / QS2) * __ldcg(g_s1 + tid);
        if (tid < NBLK)  v -= INV_T * __ldcg(g_dgpart + tid)
                            + halfT2 * __ldcg(g_dg2part + tid);
        red[tid] = v;
        __syncthreads();
#pragma unroll
        for (int s = 128; s; s >>= 1) {
            if (tid < s) red[tid] += red[tid + s];
            __syncthreads();
        }
        if (tid == 0) {
            out[0] = logf((float)NPTS) + red[0] / ((float)NPTS * (float)NB);
            g_ctr = 0;      // reset for next graph replay
        }
    }
}

// ===========================================================================
extern "C" void kernel_launch(void* const* d_in, const int* in_sizes, int n_in,
                              void* d_out, int out_size) {
    const float* q = (const float*)d_in[0];
    const float* k = (const float*)d_in[1];
    float* out = (float*)d_out;
    (void)in_sizes; (void)n_in; (void)out_size;

    cudaFuncSetAttribute(k_main, cudaFuncAttributeMaxDynamicSharedMemorySize,
                         SB_TOTAL);

    k_main<<<dim3(MC, BATCH), 512, SB_TOTAL>>>(q, k);

    // PDL launch for the tail: launches while k_main drains
    cudaLaunchConfig_t cfg = {};
    cfg.gridDim = dim3(TAILB, 1, 1);
    cfg.blockDim = dim3(256, 1, 1);
    cfg.dynamicSmemBytes = 0;
    cfg.stream = 0;
    cudaLaunchAttribute at[1];
    at[0].id = cudaLaunchAttributeProgrammaticStreamSerialization;
    at[0].val.programmaticStreamSerializationAllowed = 1;
    cfg.attrs = at;
    cfg.numAttrs = 1;
    cudaLaunchKernelEx(&cfg, k_tail, out);
}

// round 15
// speedup vs baseline: 1.0929x; 1.0929x over previous
#include <cuda_runtime.h>
#include <cuda_bf16.h>
#include <cuda_fp8.h>
#include <cstdint>
#include <math.h>

#define BATCH 4
#define DIM   128
#define NPTS  4096
#define NB    (BATCH*NPTS)
#define MC    32            // m-chunks
#define MPER  128           // m per chunk
#define NBLK  (MC*BATCH)    // 128
#define INV_T 14.285714285714286f
#define QS    64.0f         // fp8 pre-scale (folded out in finisher)
#define QS4   16777216.0f   // 64^4
#define QS2   4096.0f       // 64^2
#define TAILB 260           // 256 frobenius blocks + 4 s1 blocks

// fp8 tile: [128 d rows][128 m + 16 pad] = 144 B row stride (conflict-free LDSM)
#define TSTRIDE 144

// ---- device scratch (no allocations allowed) ----
__device__ uint32_t g_gpart[2097152];      // bf16x2 gram partials, 8.4 MB
__device__ float g_spart[2*BATCH*MC*DIM];  // per-d column-sum partials (x64 scaled)
__device__ float g_dgpart[NBLK];
__device__ float g_dg2part[NBLK];
__device__ float g_fpart[256];
__device__ float g_s1[BATCH];
__device__ unsigned int g_ctr;             // zero-init; reset by finisher

// =============================== PTX helpers ===============================
__device__ __forceinline__ uint32_t smem_u32(const void* p) {
    uint32_t a;
    asm("{ .reg .u64 t; cvta.to.shared.u64 t, %1; cvt.u32.u64 %0, t; }"
        : "=r"(a) : "l"(p));
    return a;
}
__device__ __forceinline__ void ldsm_x4(uint32_t* r, uint32_t addr) {
    asm volatile("ldmatrix.sync.aligned.m8n8.x4.shared.b16 {%0,%1,%2,%3}, [%4];"
        : "=r"(r[0]), "=r"(r[1]), "=r"(r[2]), "=r"(r[3]) : "r"(addr));
}
__device__ __forceinline__ void mma_fp8(float* c, const uint32_t* a,
                                        uint32_t b0, uint32_t b1) {
    asm volatile("mma.sync.aligned.m16n8k32.row.col.f32.e4m3.e4m3.f32 "
        "{%0,%1,%2,%3}, {%4,%5,%6,%7}, {%8,%9}, {%0,%1,%2,%3};"
        : "+f"(c[0]), "+f"(c[1]), "+f"(c[2]), "+f"(c[3])
        : "r"(a[0]), "r"(a[1]), "r"(a[2]), "r"(a[3]), "r"(b0), "r"(b1));
}
__device__ __forceinline__ uint32_t bf2u(__nv_bfloat162 v) {
    return *(uint32_t*)&v;
}
__device__ __forceinline__ float blo(uint32_t u) { return __uint_as_float(u << 16); }
__device__ __forceinline__ float bhi(uint32_t u) { return __uint_as_float(u & 0xffff0000u); }
__device__ __forceinline__ uint32_t pack_fp8x4(float a, float b, float c, float d) {
    __nv_fp8x2_storage_t lo =
        __nv_cvt_float2_to_fp8x2(make_float2(a, b), __NV_SATFINITE, __NV_E4M3);
    __nv_fp8x2_storage_t hi =
        __nv_cvt_float2_to_fp8x2(make_float2(c, d), __NV_SATFINITE, __NV_E4M3);
    return (uint32_t)lo | ((uint32_t)hi << 16);
}

// smem byte layout (scratch aliases tile region — each alias dead before reuse)
#define SB_QB   0            // fp8 q tile, 18432
#define SB_KB   18432        // fp8 k tile -> 36864
#define SB_RQ   0            // alias: 16 warps x 128 m x 4B = 8192
#define SB_RK   8192
#define SB_RD   16384        // ends 24576 < 36864
#define SB_IQ   36864        // 128 f (x64-scaled inv norms)
#define SB_IK   37376
#define SB_SCR  37888        // 16 floats -> 37952
#define SB_CS   37952        // column-sum scratch: 32 lanes x 257 f = 32896
#define SB_TOTAL 70848

// ===========================================================================
// k_main: 512 thr, grid (32,4). EXACT R13 code (measured best) + one trailing
// griddepcontrol.launch_dependents.
// ===========================================================================
__global__ __launch_bounds__(512, 1) void k_main(const float* __restrict__ q,
                                                 const float* __restrict__ k) {
    extern __shared__ char smc[];
    char*  qb  = smc + SB_QB;
    char*  kb  = smc + SB_KB;
    float* rq  = (float*)(smc + SB_RQ);
    float* rk  = (float*)(smc + SB_RK);
    float* rd  = (float*)(smc + SB_RD);
    float* iq  = (float*)(smc + SB_IQ);
    float* ik  = (float*)(smc + SB_IK);
    float* scr = (float*)(smc + SB_SCR);
    float* csS = (float*)(smc + SB_CS);    // [lane][257], slot = which*128+d

    int tid = threadIdx.x, wid = tid >> 5, lane = tid & 31;
    int cblk = blockIdx.x, b = blockIdx.y;
    int m0 = cblk * MPER;
    int m4 = lane * 4;

    // ---- phase 1: single global read; norm/dot partials; raw bf16 in regs
    const float* qg = q + (size_t)b * DIM * NPTS + m0 + m4;
    const float* kg = k + (size_t)b * DIM * NPTS + m0 + m4;
    uint2 qr[8], kr[8];
    float sq0 = 0.f, sq1 = 0.f, sq2 = 0.f, sq3 = 0.f;
    float sk0 = 0.f, sk1 = 0.f, sk2 = 0.f, sk3 = 0.f;
    float dt0 = 0.f, dt1 = 0.f, dt2 = 0.f, dt3 = 0.f;
#pragma unroll
    for (int it = 0; it < 8; it++) {
        int d = it * 16 + wid;
        float4 vq = *(const float4*)(qg + (size_t)d * NPTS);
        float4 vk = *(const float4*)(kg + (size_t)d * NPTS);
        sq0 += fabsf(vq.x); sq1 += fabsf(vq.y); sq2 += fabsf(vq.z); sq3 += fabsf(vq.w);
        sk0 += fabsf(vk.x); sk1 += fabsf(vk.y); sk2 += fabsf(vk.z); sk3 += fabsf(vk.w);
        dt0 += vq.x * vk.x; dt1 += vq.y * vk.y; dt2 += vq.z * vk.z; dt3 += vq.w * vk.w;
        qr[it] = make_uint2(bf2u(__float22bfloat162_rn(make_float2(vq.x, vq.y))),
                            bf2u(__float22bfloat162_rn(make_float2(vq.z, vq.w))));
        kr[it] = make_uint2(bf2u(__float22bfloat162_rn(make_float2(vk.x, vk.y))),
                            bf2u(__float22bfloat162_rn(make_float2(vk.z, vk.w))));
    }
    *(float4*)(rq + wid * 128 + m4) = make_float4(sq0, sq1, sq2, sq3);
    *(float4*)(rk + wid * 128 + m4) = make_float4(sk0, sk1, sk2, sk3);
    *(float4*)(rd + wid * 128 + m4) = make_float4(dt0, dt1, dt2, dt3);
    __syncthreads();

    // ---- phase 2: reduce over 16 warps; inv norms (x64 for fp8); dg/dg2 ---
    if (tid < 128) {
        float sq = 0.f, sk = 0.f, dt = 0.f;
#pragma unroll
        for (int w = 0; w < 16; w++) {
            sq += rq[w * 128 + tid];
            sk += rk[w * 128 + tid];
            dt += rd[w * 128 + tid];
        }
        float iqv = 1.f / fmaxf(sq, 1e-12f);
        float ikv = 1.f / fmaxf(sk, 1e-12f);
        iq[tid] = iqv * QS;
        ik[tid] = ikv * QS;
        float dg = dt * iqv * ikv;          // exact fp32, unscaled
        float dg2 = dg * dg;
#pragma unroll
        for (int o = 16; o; o >>= 1) {
            dg  += __shfl_down_sync(0xffffffffu, dg, o);
            dg2 += __shfl_down_sync(0xffffffffu, dg2, o);
        }
        if (lane == 0) { scr[wid] = dg; scr[4 + wid] = dg2; }
    }
    __syncthreads();
    if (tid == 0) {
        int blk = b * MC + cblk;
        g_dgpart[blk]  = scr[0] + scr[1] + scr[2] + scr[3];
        g_dg2part[blk] = scr[4] + scr[5] + scr[6] + scr[7];
    }

    // ---- phase 3: normalize (fp32) -> fp8 tiles; cs partials to smem ------
    {
        float4 iqv = *(float4*)(iq + m4);
        float4 ikv = *(float4*)(ik + m4);
#pragma unroll
        for (int it = 0; it < 8; it++) {
            int d = it * 16 + wid;
            float x0 = blo(qr[it].x) * iqv.x, x1 = bhi(qr[it].x) * iqv.y;
            float x2 = blo(qr[it].y) * iqv.z, x3 = bhi(qr[it].y) * iqv.w;
            float y0 = blo(kr[it].x) * ikv.x, y1 = bhi(kr[it].x) * ikv.y;
            float y2 = blo(kr[it].y) * ikv.z, y3 = bhi(kr[it].y) * ikv.w;
            uint32_t off = (uint32_t)(d * TSTRIDE) + (uint32_t)m4;
            *(uint32_t*)(qb + off) = pack_fp8x4(x0, x1, x2, x3);
            *(uint32_t*)(kb + off) = pack_fp8x4(y0, y1, y2, y3);
            csS[lane * 257 + d]       = (x0 + x1) + (x2 + x3);
            csS[lane * 257 + 128 + d] = (y0 + y1) + (y2 + y3);
        }
    }
    __syncthreads();

    // ---- phase 3b: column-sum reduce (256 threads, conflict-free LDS) -----
    if (tid < 256) {
        float a0 = 0.f, a1 = 0.f, a2 = 0.f, a3 = 0.f;
#pragma unroll
        for (int l = 0; l < 32; l += 4) {
            a0 += csS[(l + 0) * 257 + tid];
            a1 += csS[(l + 1) * 257 + tid];
            a2 += csS[(l + 2) * 257 + tid];
            a3 += csS[(l + 3) * 257 + tid];
        }
        int which = tid >> 7, d = tid & 127;
        g_spart[((size_t)(which * BATCH + b) * MC + cblk) * DIM + d]
            = (a0 + a1) + (a2 + a3);
    }
    // no extra sync: phase 4 reads only the tiles (already synced)

    // ---- phase 4: fp8 grams. warps 0-7 -> Gq, 8-15 -> Gk -----------------
    int which = wid >> 3;
    int wrow = wid & 7;
    uint32_t base = smem_u32(which ? kb : qb);
    int grp = lane >> 3;
    uint32_t arow_off = (uint32_t)((wrow * 16 + ((grp & 1) << 3) + (lane & 7)) * TSTRIDE
                                   + ((grp >> 1) << 4));
    uint32_t brow_off = (uint32_t)((((grp & 1) << 3) + (lane & 7)) * TSTRIDE
                                   + ((grp >> 1) << 4));
    int r  = lane >> 2;
    int cp = (lane & 3) << 1;
    int d1r = wrow * 16 + r;

    float c[64];
#pragma unroll
    for (int i = 0; i < 64; i++) c[i] = 0.f;

#pragma unroll
    for (int ks = 0; ks < 4; ks++) {           // K=32 fp8 per mma, 4*32=128 m
        uint32_t a[4];
        ldsm_x4(a, base + arow_off + ks * 32);
#pragma unroll
        for (int bt = 0; bt < 8; bt++) {
            uint32_t bb[4];
            ldsm_x4(bb, base + brow_off + (uint32_t)(bt * 16 * TSTRIDE) + ks * 32);
            mma_fp8(c + bt * 8,     a, bb[0], bb[2]);
            mma_fp8(c + bt * 8 + 4, a, bb[1], bb[3]);
        }
    }

    uint32_t* outp = g_gpart
        + ((size_t)(which * BATCH + b) * MC + cblk) * 8192;   // u32 pairs
#pragma unroll
    for (int bt = 0; bt < 8; bt++) {
#pragma unroll
        for (int h = 0; h < 2; h++) {
            int col = bt * 16 + h * 8 + cp;
            const float* cc = c + bt * 8 + h * 4;
            outp[(d1r * 128 + col) >> 1] =
                bf2u(__float22bfloat162_rn(make_float2(cc[0], cc[1])));
            outp[((d1r + 8) * 128 + col) >> 1] =
                bf2u(__float22bfloat162_rn(make_float2(cc[2], cc[3])));
        }
    }

    // PDL: this block's results are written — signal dependent launch.
    asm volatile("griddepcontrol.launch_dependents;" ::: "memory");
}

// ===========================================================================
// k_tail: grid 260, 256 thr. IDENTICAL to R13.
// ===========================================================================
__global__ __launch_bounds__(256) void k_tail(float* __restrict__ out) {
    __shared__ float smQ[256][8];
    __shared__ float smK[256][8];
    __shared__ float rr[8];
    __shared__ bool lastf;
    int tid = threadIdx.x, lane = tid & 31;
    int blk = blockIdx.x;

    // PDL: ensure k_main's grid is complete + memory visible
    asm volatile("griddepcontrol.wait;" ::: "memory");

    if (blk < 256) {
        int bb = blk >> 6;                          // batch
        int pos = (blk & 63) * 32 + (tid & 31);     // uint4 position 0..2047
        int cs = tid >> 5;                          // csplit 0..7 (4 chunks)
        const uint4* bq = (const uint4*)g_gpart
                        + (size_t)(0 * BATCH + bb) * MC * 2048 + pos
                        + (size_t)(cs * 4) * 2048;
        const uint4* bk = (const uint4*)g_gpart
                        + (size_t)(1 * BATCH + bb) * MC * 2048 + pos
                        + (size_t)(cs * 4) * 2048;
        uint4 q0 = __ldcg(bq);
        uint4 q1 = __ldcg(bq + 2048);
        uint4 q2 = __ldcg(bq + 2 * 2048);
        uint4 q3 = __ldcg(bq + 3 * 2048);
        uint4 k0 = __ldcg(bk);
        uint4 k1 = __ldcg(bk + 2048);
        uint4 k2 = __ldcg(bk + 2 * 2048);
        uint4 k3 = __ldcg(bk + 3 * 2048);

        float* oq = &smQ[tid][0];
        float* ok = &smK[tid][0];
        oq[0] = (blo(q0.x) + blo(q1.x)) + (blo(q2.x) + blo(q3.x));
        oq[1] = (bhi(q0.x) + bhi(q1.x)) + (bhi(q2.x) + bhi(q3.x));
        oq[2] = (blo(q0.y) + blo(q1.y)) + (blo(q2.y) + blo(q3.y));
        oq[3] = (bhi(q0.y) + bhi(q1.y)) + (bhi(q2.y) + bhi(q3.y));
        oq[4] = (blo(q0.z) + blo(q1.z)) + (blo(q2.z) + blo(q3.z));
        oq[5] = (bhi(q0.z) + bhi(q1.z)) + (bhi(q2.z) + bhi(q3.z));
        oq[6] = (blo(q0.w) + blo(q1.w)) + (blo(q2.w) + blo(q3.w));
        oq[7] = (bhi(q0.w) + bhi(q1.w)) + (bhi(q2.w) + bhi(q3.w));
        ok[0] = (blo(k0.x) + blo(k1.x)) + (blo(k2.x) + blo(k3.x));
        ok[1] = (bhi(k0.x) + bhi(k1.x)) + (bhi(k2.x) + bhi(k3.x));
        ok[2] = (blo(k0.y) + blo(k1.y)) + (blo(k2.y) + blo(k3.y));
        ok[3] = (bhi(k0.y) + bhi(k1.y)) + (bhi(k2.y) + bhi(k3.y));
        ok[4] = (blo(k0.z) + blo(k1.z)) + (blo(k2.z) + blo(k3.z));
        ok[5] = (bhi(k0.z) + bhi(k1.z)) + (bhi(k2.z) + bhi(k3.z));
        ok[6] = (blo(k0.w) + blo(k1.w)) + (blo(k2.w) + blo(k3.w));
        ok[7] = (bhi(k0.w) + bhi(k1.w)) + (bhi(k2.w) + bhi(k3.w));
        __syncthreads();

        // combine 8 csplits in fixed order (full 32-chunk sums), then product
        int lp = tid >> 3, e = tid & 7;             // local pos, elem
        float aq = 0.f, ak = 0.f;
#pragma unroll
        for (int s = 0; s < 8; s++) {
            aq += smQ[s * 32 + lp][e];
            ak += smK[s * 32 + lp][e];
        }
        float f = aq * ak;
#pragma unroll
        for (int o = 16; o; o >>= 1) f += __shfl_down_sync(0xffffffffu, f, o);
        if (lane == 0) rr[tid >> 5] = f;
        __syncthreads();
        if (tid == 0) {
            float t = 0.f;
#pragma unroll
            for (int i = 0; i < 8; i++) t += rr[i];
            g_fpart[blk] = t;
        }
    } else {
        int b = blk - 256;
        float* SQ = &smQ[0][0];                     // 512 floats used
        float* SK = &smK[0][0];
        if (tid < 128) {
            int d4 = tid & 31, half = tid >> 5;     // chunk 4-way split
            const float4* pq = (const float4*)(g_spart
                + (size_t)(0 * BATCH + b) * MC * DIM) + d4 + (size_t)(half * 8) * 32;
            const float4* pk = (const float4*)(g_spart
                + (size_t)(1 * BATCH + b) * MC * DIM) + d4 + (size_t)(half * 8) * 32;
            float4 sq = make_float4(0.f, 0.f, 0.f, 0.f);
            float4 sk = make_float4(0.f, 0.f, 0.f, 0.f);
#pragma unroll
            for (int c = 0; c < 8; c++) {
                float4 tq = __ldcg(pq + (size_t)c * 32);
                float4 tk = __ldcg(pk + (size_t)c * 32);
                sq.x += tq.x; sq.y += tq.y; sq.z += tq.z; sq.w += tq.w;
                sk.x += tk.x; sk.y += tk.y; sk.z += tk.z; sk.w += tk.w;
            }
            // layout: [d (=d4*4+e)][half] -> SQ[(d4*4+e)*4+half]
            SQ[(d4 * 4 + 0) * 4 + half] = sq.x;
            SQ[(d4 * 4 + 1) * 4 + half] = sq.y;
            SQ[(d4 * 4 + 2) * 4 + half] = sq.z;
            SQ[(d4 * 4 + 3) * 4 + half] = sq.w;
            SK[(d4 * 4 + 0) * 4 + half] = sk.x;
            SK[(d4 * 4 + 1) * 4 + half] = sk.y;
            SK[(d4 * 4 + 2) * 4 + half] = sk.z;
            SK[(d4 * 4 + 3) * 4 + half] = sk.w;
        }
        __syncthreads();
        if (tid < 128) {
            // full 32-chunk sums per d (fixed order), then product
            float aq = ((SQ[tid * 4 + 0] + SQ[tid * 4 + 1])
                      + (SQ[tid * 4 + 2] + SQ[tid * 4 + 3]));
            float ak = ((SK[tid * 4 + 0] + SK[tid * 4 + 1])
                      + (SK[tid * 4 + 2] + SK[tid * 4 + 3]));
            float v = aq * ak;
#pragma unroll
            for (int o = 16; o; o >>= 1)
                v += __shfl_down_sync(0xffffffffu, v, o);
            if (lane == 0) rr[tid >> 5] = v;
        }
        __syncthreads();
        if (tid == 0) g_s1[b] = rr[0] + rr[1] + rr[2] + rr[3];
    }

    // ---- finisher: last of the 260 blocks computes the loss ---------------
    __syncthreads();
    if (tid == 0) {
        __threadfence();
        lastf = (atomicAdd(&g_ctr, 1u) == (unsigned)(TAILB - 1));
    }
    __syncthreads();
    if (lastf) {
        float* red = &smQ[0][0];                    // 256 floats
        const float halfT2 = 0.5f * INV_T * INV_T;
        float v = (halfT2 / QS4) * __ldcg(g_fpart + tid);
        if (tid < BATCH) v += (INV_T / QS2) * __ldcg(g_s1 + tid);
        if (tid < NBLK)  v -= INV_T * __ldcg(g_dgpart + tid)
                            + halfT2 * __ldcg(g_dg2part + tid);
        red[tid] = v;
        __syncthreads();
#pragma unroll
        for (int s = 128; s; s >>= 1) {
            if (tid < s) red[tid] += red[tid + s];
            __syncthreads();
        }
        if (tid == 0) {
            out[0] = logf((float)NPTS) + red[0] / ((float)NPTS * (float)NB);
            g_ctr = 0;      // reset for next graph replay
        }
    }
}

// ===========================================================================
extern "C" void kernel_launch(void* const* d_in, const int* in_sizes, int n_in,
                              void* d_out, int out_size) {
    const float* q = (const float*)d_in[0];
    const float* k = (const float*)d_in[1];
    float* out = (float*)d_out;
    (void)in_sizes; (void)n_in; (void)out_size;

    cudaFuncSetAttribute(k_main, cudaFuncAttributeMaxDynamicSharedMemorySize,
                         SB_TOTAL);

    k_main<<<dim3(MC, BATCH), 512, SB_TOTAL>>>(q, k);

    // PDL launch for the tail: launches while k_main drains
    cudaLaunchConfig_t cfg = {};
    cfg.gridDim = dim3(TAILB, 1, 1);
    cfg.blockDim = dim3(256, 1, 1);
    cfg.dynamicSmemBytes = 0;
    cfg.stream = 0;
    cudaLaunchAttribute at[1];
    at[0].id = cudaLaunchAttributeProgrammaticStreamSerialization;
    at[0].val.programmaticStreamSerializationAllowed = 1;
    cfg.attrs = at;
    cfg.numAttrs = 1;
    cudaLaunchKernelEx(&cfg, k_tail, out);
}

// round 16
// speedup vs baseline: 1.2254x; 1.1212x over previous
#include <cuda_runtime.h>
#include <cuda_bf16.h>
#include <cuda_fp8.h>
#include <cstdint>
#include <math.h>

#define BATCH 4
#define DIM   128
#define NPTS  4096
#define NB    (BATCH*NPTS)
#define MC    32            // m-chunks
#define MPER  128           // m per chunk
#define NBLK  (MC*BATCH)    // 128
#define INV_T 14.285714285714286f
#define QS    64.0f         // fp8 pre-scale (folded out in finisher)
#define QS4   16777216.0f   // 64^4
#define QS2   4096.0f       // 64^2
#define FROB  128           // frobenius blocks (32 per batch)
#define TAILB 132           // + 4 s1 blocks = single wave (<=148 SMs)

// fp8 tile: [128 d rows][128 m + 16 pad] = 144 B row stride (conflict-free LDSM)
#define TSTRIDE 144

// ---- device scratch (no allocations allowed) ----
__device__ uint32_t g_gpart[2097152];      // bf16x2 gram partials, 8.4 MB
__device__ float g_spart[2*BATCH*MC*DIM];  // per-d column-sum partials (x64 scaled)
__device__ float g_dgpart[NBLK];
__device__ float g_dg2part[NBLK];
__device__ float g_fpart[FROB];
__device__ float g_s1[BATCH];
__device__ unsigned int g_ctr;             // zero-init; reset by finisher

// =============================== PTX helpers ===============================
__device__ __forceinline__ uint32_t smem_u32(const void* p) {
    uint32_t a;
    asm("{ .reg .u64 t; cvta.to.shared.u64 t, %1; cvt.u32.u64 %0, t; }"
        : "=r"(a) : "l"(p));
    return a;
}
__device__ __forceinline__ void ldsm_x4(uint32_t* r, uint32_t addr) {
    asm volatile("ldmatrix.sync.aligned.m8n8.x4.shared.b16 {%0,%1,%2,%3}, [%4];"
        : "=r"(r[0]), "=r"(r[1]), "=r"(r[2]), "=r"(r[3]) : "r"(addr));
}
__device__ __forceinline__ void mma_fp8(float* c, const uint32_t* a,
                                        uint32_t b0, uint32_t b1) {
    asm volatile("mma.sync.aligned.m16n8k32.row.col.f32.e4m3.e4m3.f32 "
        "{%0,%1,%2,%3}, {%4,%5,%6,%7}, {%8,%9}, {%0,%1,%2,%3};"
        : "+f"(c[0]), "+f"(c[1]), "+f"(c[2]), "+f"(c[3])
        : "r"(a[0]), "r"(a[1]), "r"(a[2]), "r"(a[3]), "r"(b0), "r"(b1));
}
__device__ __forceinline__ uint32_t bf2u(__nv_bfloat162 v) {
    return *(uint32_t*)&v;
}
__device__ __forceinline__ float blo(uint32_t u) { return __uint_as_float(u << 16); }
__device__ __forceinline__ float bhi(uint32_t u) { return __uint_as_float(u & 0xffff0000u); }
__device__ __forceinline__ uint32_t pack_fp8x4(float a, float b, float c, float d) {
    __nv_fp8x2_storage_t lo =
        __nv_cvt_float2_to_fp8x2(make_float2(a, b), __NV_SATFINITE, __NV_E4M3);
    __nv_fp8x2_storage_t hi =
        __nv_cvt_float2_to_fp8x2(make_float2(c, d), __NV_SATFINITE, __NV_E4M3);
    return (uint32_t)lo | ((uint32_t)hi << 16);
}

// smem byte layout (scratch aliases tile region — each alias dead before reuse)
#define SB_QB   0            // fp8 q tile, 18432
#define SB_KB   18432        // fp8 k tile -> 36864
#define SB_RQ   0            // alias: 16 warps x 128 m x 4B = 8192
#define SB_RK   8192
#define SB_RD   16384        // ends 24576 < 36864
#define SB_IQ   36864        // 128 f (x64-scaled inv norms)
#define SB_IK   37376
#define SB_SCR  37888        // 16 floats -> 37952
#define SB_CS   37952        // column-sum scratch: 32 lanes x 257 f = 32896
#define SB_TOTAL 70848

// ===========================================================================
// k_main: 512 thr, grid (32,4). EXACT R13 code (measured best 16.9us total).
// NO launch_dependents (proven harmful: early tail blocks steal residency).
// ===========================================================================
__global__ __launch_bounds__(512, 1) void k_main(const float* __restrict__ q,
                                                 const float* __restrict__ k) {
    extern __shared__ char smc[];
    char*  qb  = smc + SB_QB;
    char*  kb  = smc + SB_KB;
    float* rq  = (float*)(smc + SB_RQ);
    float* rk  = (float*)(smc + SB_RK);
    float* rd  = (float*)(smc + SB_RD);
    float* iq  = (float*)(smc + SB_IQ);
    float* ik  = (float*)(smc + SB_IK);
    float* scr = (float*)(smc + SB_SCR);
    float* csS = (float*)(smc + SB_CS);    // [lane][257], slot = which*128+d

    int tid = threadIdx.x, wid = tid >> 5, lane = tid & 31;
    int cblk = blockIdx.x, b = blockIdx.y;
    int m0 = cblk * MPER;
    int m4 = lane * 4;

    // ---- phase 1: single global read; norm/dot partials; raw bf16 in regs
    const float* qg = q + (size_t)b * DIM * NPTS + m0 + m4;
    const float* kg = k + (size_t)b * DIM * NPTS + m0 + m4;
    uint2 qr[8], kr[8];
    float sq0 = 0.f, sq1 = 0.f, sq2 = 0.f, sq3 = 0.f;
    float sk0 = 0.f, sk1 = 0.f, sk2 = 0.f, sk3 = 0.f;
    float dt0 = 0.f, dt1 = 0.f, dt2 = 0.f, dt3 = 0.f;
#pragma unroll
    for (int it = 0; it < 8; it++) {
        int d = it * 16 + wid;
        float4 vq = *(const float4*)(qg + (size_t)d * NPTS);
        float4 vk = *(const float4*)(kg + (size_t)d * NPTS);
        sq0 += fabsf(vq.x); sq1 += fabsf(vq.y); sq2 += fabsf(vq.z); sq3 += fabsf(vq.w);
        sk0 += fabsf(vk.x); sk1 += fabsf(vk.y); sk2 += fabsf(vk.z); sk3 += fabsf(vk.w);
        dt0 += vq.x * vk.x; dt1 += vq.y * vk.y; dt2 += vq.z * vk.z; dt3 += vq.w * vk.w;
        qr[it] = make_uint2(bf2u(__float22bfloat162_rn(make_float2(vq.x, vq.y))),
                            bf2u(__float22bfloat162_rn(make_float2(vq.z, vq.w))));
        kr[it] = make_uint2(bf2u(__float22bfloat162_rn(make_float2(vk.x, vk.y))),
                            bf2u(__float22bfloat162_rn(make_float2(vk.z, vk.w))));
    }
    *(float4*)(rq + wid * 128 + m4) = make_float4(sq0, sq1, sq2, sq3);
    *(float4*)(rk + wid * 128 + m4) = make_float4(sk0, sk1, sk2, sk3);
    *(float4*)(rd + wid * 128 + m4) = make_float4(dt0, dt1, dt2, dt3);
    __syncthreads();

    // ---- phase 2: reduce over 16 warps; inv norms (x64 for fp8); dg/dg2 ---
    if (tid < 128) {
        float sq = 0.f, sk = 0.f, dt = 0.f;
#pragma unroll
        for (int w = 0; w < 16; w++) {
            sq += rq[w * 128 + tid];
            sk += rk[w * 128 + tid];
            dt += rd[w * 128 + tid];
        }
        float iqv = 1.f / fmaxf(sq, 1e-12f);
        float ikv = 1.f / fmaxf(sk, 1e-12f);
        iq[tid] = iqv * QS;
        ik[tid] = ikv * QS;
        float dg = dt * iqv * ikv;          // exact fp32, unscaled
        float dg2 = dg * dg;
#pragma unroll
        for (int o = 16; o; o >>= 1) {
            dg  += __shfl_down_sync(0xffffffffu, dg, o);
            dg2 += __shfl_down_sync(0xffffffffu, dg2, o);
        }
        if (lane == 0) { scr[wid] = dg; scr[4 + wid] = dg2; }
    }
    __syncthreads();
    if (tid == 0) {
        int blk = b * MC + cblk;
        g_dgpart[blk]  = scr[0] + scr[1] + scr[2] + scr[3];
        g_dg2part[blk] = scr[4] + scr[5] + scr[6] + scr[7];
    }

    // ---- phase 3: normalize (fp32) -> fp8 tiles; cs partials to smem ------
    {
        float4 iqv = *(float4*)(iq + m4);
        float4 ikv = *(float4*)(ik + m4);
#pragma unroll
        for (int it = 0; it < 8; it++) {
            int d = it * 16 + wid;
            float x0 = blo(qr[it].x) * iqv.x, x1 = bhi(qr[it].x) * iqv.y;
            float x2 = blo(qr[it].y) * iqv.z, x3 = bhi(qr[it].y) * iqv.w;
            float y0 = blo(kr[it].x) * ikv.x, y1 = bhi(kr[it].x) * ikv.y;
            float y2 = blo(kr[it].y) * ikv.z, y3 = bhi(kr[it].y) * ikv.w;
            uint32_t off = (uint32_t)(d * TSTRIDE) + (uint32_t)m4;
            *(uint32_t*)(qb + off) = pack_fp8x4(x0, x1, x2, x3);
            *(uint32_t*)(kb + off) = pack_fp8x4(y0, y1, y2, y3);
            csS[lane * 257 + d]       = (x0 + x1) + (x2 + x3);
            csS[lane * 257 + 128 + d] = (y0 + y1) + (y2 + y3);
        }
    }
    __syncthreads();

    // ---- phase 3b: column-sum reduce (256 threads, conflict-free LDS) -----
    if (tid < 256) {
        float a0 = 0.f, a1 = 0.f, a2 = 0.f, a3 = 0.f;
#pragma unroll
        for (int l = 0; l < 32; l += 4) {
            a0 += csS[(l + 0) * 257 + tid];
            a1 += csS[(l + 1) * 257 + tid];
            a2 += csS[(l + 2) * 257 + tid];
            a3 += csS[(l + 3) * 257 + tid];
        }
        int which = tid >> 7, d = tid & 127;
        g_spart[((size_t)(which * BATCH + b) * MC + cblk) * DIM + d]
            = (a0 + a1) + (a2 + a3);
    }
    // no extra sync: phase 4 reads only the tiles (already synced)

    // ---- phase 4: fp8 grams. warps 0-7 -> Gq, 8-15 -> Gk -----------------
    int which = wid >> 3;
    int wrow = wid & 7;
    uint32_t base = smem_u32(which ? kb : qb);
    int grp = lane >> 3;
    uint32_t arow_off = (uint32_t)((wrow * 16 + ((grp & 1) << 3) + (lane & 7)) * TSTRIDE
                                   + ((grp >> 1) << 4));
    uint32_t brow_off = (uint32_t)((((grp & 1) << 3) + (lane & 7)) * TSTRIDE
                                   + ((grp >> 1) << 4));
    int r  = lane >> 2;
    int cp = (lane & 3) << 1;
    int d1r = wrow * 16 + r;

    float c[64];
#pragma unroll
    for (int i = 0; i < 64; i++) c[i] = 0.f;

#pragma unroll
    for (int ks = 0; ks < 4; ks++) {           // K=32 fp8 per mma, 4*32=128 m
        uint32_t a[4];
        ldsm_x4(a, base + arow_off + ks * 32);
#pragma unroll
        for (int bt = 0; bt < 8; bt++) {
            uint32_t bb[4];
            ldsm_x4(bb, base + brow_off + (uint32_t)(bt * 16 * TSTRIDE) + ks * 32);
            mma_fp8(c + bt * 8,     a, bb[0], bb[2]);
            mma_fp8(c + bt * 8 + 4, a, bb[1], bb[3]);
        }
    }

    uint32_t* outp = g_gpart
        + ((size_t)(which * BATCH + b) * MC + cblk) * 8192;   // u32 pairs
#pragma unroll
    for (int bt = 0; bt < 8; bt++) {
#pragma unroll
        for (int h = 0; h < 2; h++) {
            int col = bt * 16 + h * 8 + cp;
            const float* cc = c + bt * 8 + h * 4;
            outp[(d1r * 128 + col) >> 1] =
                bf2u(__float22bfloat162_rn(make_float2(cc[0], cc[1])));
            outp[((d1r + 8) * 128 + col) >> 1] =
                bf2u(__float22bfloat162_rn(make_float2(cc[2], cc[3])));
        }
    }
}

// ===========================================================================
// k_tail: grid 132 (single wave), 256 thr. PDL secondary (implicit signal).
//  blk < 128: frobenius. bb = blk>>5; 64 uint4 positions; thread =
//    (pos 0..63) x (csplit 0..3 of 8 chunks); 16 INDEPENDENT __ldcg uint4
//    loads (8 q + 8 k). Sum-then-product via smem (fixed order).
//  blk >= 128: s1 for batch blk-128.
//  Counter finisher (132) computes the final scalar.
// ===========================================================================
__global__ __launch_bounds__(256) void k_tail(float* __restrict__ out) {
    __shared__ float smQ[256][8];
    __shared__ float smK[256][8];
    __shared__ float rr[8];
    __shared__ bool lastf;
    int tid = threadIdx.x, lane = tid & 31;
    int blk = blockIdx.x;

    // PDL: ensure k_main's grid is complete + memory visible
    asm volatile("griddepcontrol.wait;" ::: "memory");

    if (blk < FROB) {
        int bb = blk >> 5;                          // batch
        int pos = (blk & 31) * 64 + (tid & 63);     // uint4 position 0..2047
        int cs = tid >> 6;                          // csplit 0..3 (8 chunks)
        const uint4* bq = (const uint4*)g_gpart
                        + (size_t)(0 * BATCH + bb) * MC * 2048 + pos
                        + (size_t)(cs * 8) * 2048;
        const uint4* bk = (const uint4*)g_gpart
                        + (size_t)(1 * BATCH + bb) * MC * 2048 + pos
                        + (size_t)(cs * 8) * 2048;
        // 16 independent loads
        uint4 q0 = __ldcg(bq);
        uint4 q1 = __ldcg(bq + 2048);
        uint4 q2 = __ldcg(bq + 2 * 2048);
        uint4 q3 = __ldcg(bq + 3 * 2048);
        uint4 q4 = __ldcg(bq + 4 * 2048);
        uint4 q5 = __ldcg(bq + 5 * 2048);
        uint4 q6 = __ldcg(bq + 6 * 2048);
        uint4 q7 = __ldcg(bq + 7 * 2048);
        uint4 k0 = __ldcg(bk);
        uint4 k1 = __ldcg(bk + 2048);
        uint4 k2 = __ldcg(bk + 2 * 2048);
        uint4 k3 = __ldcg(bk + 3 * 2048);
        uint4 k4 = __ldcg(bk + 4 * 2048);
        uint4 k5 = __ldcg(bk + 5 * 2048);
        uint4 k6 = __ldcg(bk + 6 * 2048);
        uint4 k7 = __ldcg(bk + 7 * 2048);

        float* oq = &smQ[tid][0];
        float* ok = &smK[tid][0];
        oq[0] = ((blo(q0.x) + blo(q1.x)) + (blo(q2.x) + blo(q3.x)))
              + ((blo(q4.x) + blo(q5.x)) + (blo(q6.x) + blo(q7.x)));
        oq[1] = ((bhi(q0.x) + bhi(q1.x)) + (bhi(q2.x) + bhi(q3.x)))
              + ((bhi(q4.x) + bhi(q5.x)) + (bhi(q6.x) + bhi(q7.x)));
        oq[2] = ((blo(q0.y) + blo(q1.y)) + (blo(q2.y) + blo(q3.y)))
              + ((blo(q4.y) + blo(q5.y)) + (blo(q6.y) + blo(q7.y)));
        oq[3] = ((bhi(q0.y) + bhi(q1.y)) + (bhi(q2.y) + bhi(q3.y)))
              + ((bhi(q4.y) + bhi(q5.y)) + (bhi(q6.y) + bhi(q7.y)));
        oq[4] = ((blo(q0.z) + blo(q1.z)) + (blo(q2.z) + blo(q3.z)))
              + ((blo(q4.z) + blo(q5.z)) + (blo(q6.z) + blo(q7.z)));
        oq[5] = ((bhi(q0.z) + bhi(q1.z)) + (bhi(q2.z) + bhi(q3.z)))
              + ((bhi(q4.z) + bhi(q5.z)) + (bhi(q6.z) + bhi(q7.z)));
        oq[6] = ((blo(q0.w) + blo(q1.w)) + (blo(q2.w) + blo(q3.w)))
              + ((blo(q4.w) + blo(q5.w)) + (blo(q6.w) + blo(q7.w)));
        oq[7] = ((bhi(q0.w) + bhi(q1.w)) + (bhi(q2.w) + bhi(q3.w)))
              + ((bhi(q4.w) + bhi(q5.w)) + (bhi(q6.w) + bhi(q7.w)));
        ok[0] = ((blo(k0.x) + blo(k1.x)) + (blo(k2.x) + blo(k3.x)))
              + ((blo(k4.x) + blo(k5.x)) + (blo(k6.x) + blo(k7.x)));
        ok[1] = ((bhi(k0.x) + bhi(k1.x)) + (bhi(k2.x) + bhi(k3.x)))
              + ((bhi(k4.x) + bhi(k5.x)) + (bhi(k6.x) + bhi(k7.x)));
        ok[2] = ((blo(k0.y) + blo(k1.y)) + (blo(k2.y) + blo(k3.y)))
              + ((blo(k4.y) + blo(k5.y)) + (blo(k6.y) + blo(k7.y)));
        ok[3] = ((bhi(k0.y) + bhi(k1.y)) + (bhi(k2.y) + bhi(k3.y)))
              + ((bhi(k4.y) + bhi(k5.y)) + (bhi(k6.y) + bhi(k7.y)));
        ok[4] = ((blo(k0.z) + blo(k1.z)) + (blo(k2.z) + blo(k3.z)))
              + ((blo(k4.z) + blo(k5.z)) + (blo(k6.z) + blo(k7.z)));
        ok[5] = ((bhi(k0.z) + bhi(k1.z)) + (bhi(k2.z) + bhi(k3.z)))
              + ((bhi(k4.z) + bhi(k5.z)) + (bhi(k6.z) + bhi(k7.z)));
        ok[6] = ((blo(k0.w) + blo(k1.w)) + (blo(k2.w) + blo(k3.w)))
              + ((blo(k4.w) + blo(k5.w)) + (blo(k6.w) + blo(k7.w)));
        ok[7] = ((bhi(k0.w) + bhi(k1.w)) + (bhi(k2.w) + bhi(k3.w)))
              + ((bhi(k4.w) + bhi(k5.w)) + (bhi(k6.w) + bhi(k7.w)));
        __syncthreads();

        // combine 4 csplits in fixed order (full 32-chunk sums), then product
        float f = 0.f;
#pragma unroll
        for (int rep = 0; rep < 2; rep++) {
            int idx = tid + rep * 256;              // 0..511 = pos*8 + e
            int lp = idx >> 3, e = idx & 7;
            float aq = (smQ[lp][e] + smQ[64 + lp][e])
                     + (smQ[128 + lp][e] + smQ[192 + lp][e]);
            float ak = (smK[lp][e] + smK[64 + lp][e])
                     + (smK[128 + lp][e] + smK[192 + lp][e]);
            f += aq * ak;
        }
#pragma unroll
        for (int o = 16; o; o >>= 1) f += __shfl_down_sync(0xffffffffu, f, o);
        if (lane == 0) rr[tid >> 5] = f;
        __syncthreads();
        if (tid == 0) {
            float t = 0.f;
#pragma unroll
            for (int i = 0; i < 8; i++) t += rr[i];
            g_fpart[blk] = t;
        }
    } else {
        int b = blk - FROB;
        float* SQ = &smQ[0][0];                     // 512 floats used
        float* SK = &smK[0][0];
        if (tid < 128) {
            int d4 = tid & 31, half = tid >> 5;     // chunk 4-way split
            const float4* pq = (const float4*)(g_spart
                + (size_t)(0 * BATCH + b) * MC * DIM) + d4 + (size_t)(half * 8) * 32;
            const float4* pk = (const float4*)(g_spart
                + (size_t)(1 * BATCH + b) * MC * DIM) + d4 + (size_t)(half * 8) * 32;
            float4 sq = make_float4(0.f, 0.f, 0.f, 0.f);
            float4 sk = make_float4(0.f, 0.f, 0.f, 0.f);
#pragma unroll
            for (int c = 0; c < 8; c++) {
                float4 tq = __ldcg(pq + (size_t)c * 32);
                float4 tk = __ldcg(pk + (size_t)c * 32);
                sq.x += tq.x; sq.y += tq.y; sq.z += tq.z; sq.w += tq.w;
                sk.x += tk.x; sk.y += tk.y; sk.z += tk.z; sk.w += tk.w;
            }
            // layout: [d (=d4*4+e)][half] -> SQ[(d4*4+e)*4+half]
            SQ[(d4 * 4 + 0) * 4 + half] = sq.x;
            SQ[(d4 * 4 + 1) * 4 + half] = sq.y;
            SQ[(d4 * 4 + 2) * 4 + half] = sq.z;
            SQ[(d4 * 4 + 3) * 4 + half] = sq.w;
            SK[(d4 * 4 + 0) * 4 + half] = sk.x;
            SK[(d4 * 4 + 1) * 4 + half] = sk.y;
            SK[(d4 * 4 + 2) * 4 + half] = sk.z;
            SK[(d4 * 4 + 3) * 4 + half] = sk.w;
        }
        __syncthreads();
        if (tid < 128) {
            // full 32-chunk sums per d (fixed order), then product
            float aq = ((SQ[tid * 4 + 0] + SQ[tid * 4 + 1])
                      + (SQ[tid * 4 + 2] + SQ[tid * 4 + 3]));
            float ak = ((SK[tid * 4 + 0] + SK[tid * 4 + 1])
                      + (SK[tid * 4 + 2] + SK[tid * 4 + 3]));
            float v = aq * ak;
#pragma unroll
            for (int o = 16; o; o >>= 1)
                v += __shfl_down_sync(0xffffffffu, v, o);
            if (lane == 0) rr[tid >> 5] = v;
        }
        __syncthreads();
        if (tid == 0) g_s1[b] = rr[0] + rr[1] + rr[2] + rr[3];
    }

    // ---- finisher: last of the 132 blocks computes the loss ---------------
    __syncthreads();
    if (tid == 0) {
        __threadfence();
        lastf = (atomicAdd(&g_ctr, 1u) == (unsigned)(TAILB - 1));
    }
    __syncthreads();
    if (lastf) {
        float* red = &smQ[0][0];                    // 256 floats
        const float halfT2 = 0.5f * INV_T * INV_T;
        float v = 0.f;
        if (tid < FROB)  v += (halfT2 / QS4) * __ldcg(g_fpart + tid);
        if (tid < BATCH) v += (INV_T / QS2) * __ldcg(g_s1 + tid);
        if (tid < NBLK)  v -= INV_T * __ldcg(g_dgpart + tid)
                            + halfT2 * __ldcg(g_dg2part + tid);
        red[tid] = v;
        __syncthreads();
#pragma unroll
        for (int s = 128; s; s >>= 1) {
            if (tid < s) red[tid] += red[tid + s];
            __syncthreads();
        }
        if (tid == 0) {
            out[0] = logf((float)NPTS) + red[0] / ((float)NPTS * (float)NB);
            g_ctr = 0;      // reset for next graph replay
        }
    }
}

// ===========================================================================
extern "C" void kernel_launch(void* const* d_in, const int* in_sizes, int n_in,
                              void* d_out, int out_size) {
    const float* q = (const float*)d_in[0];
    const float* k = (const float*)d_in[1];
    float* out = (float*)d_out;
    (void)in_sizes; (void)n_in; (void)out_size;

    cudaFuncSetAttribute(k_main, cudaFuncAttributeMaxDynamicSharedMemorySize,
                         SB_TOTAL);

    k_main<<<dim3(MC, BATCH), 512, SB_TOTAL>>>(q, k);

    // PDL launch for the tail: setup overlaps k_main's drain (implicit signal)
    cudaLaunchConfig_t cfg = {};
    cfg.gridDim = dim3(TAILB, 1, 1);
    cfg.blockDim = dim3(256, 1, 1);
    cfg.dynamicSmemBytes = 0;
    cfg.stream = 0;
    cudaLaunchAttribute at[1];
    at[0].id = cudaLaunchAttributeProgrammaticStreamSerialization;
    at[0].val.programmaticStreamSerializationAllowed = 1;
    cfg.attrs = at;
    cfg.numAttrs = 1;
    cudaLaunchKernelEx(&cfg, k_tail, out);
}